// round 15
// baseline (speedup 1.0000x reference)
#include <cuda_runtime.h>
#include <cuda_fp16.h>
#include <math.h>
#include <stdint.h>

#define BB 64
#define TT 2048
#define DD 256
#define NN (BB*TT)

#define MT 128                 // frames per tile (16 tiles per batch row)
#define KC 32                  // K chunk (fp16)
#define NCH (DD/KC)            // 8 chunks
#define NTILE (NN/MT)          // 1024 tiles
#define CPB (TT/MT)            // 16 tiles per batch
#define GRID 152               // persistent CTAs (1/SM on GB300)

// ---------------- device scratch (no allocations allowed) ------------------
__device__ float g_part[NTILE * 2 * DD];  // per-tile [P_mu | P_m2]
__device__ float g_meta[NTILE * 2];       // per-tile [m_loc, Z_loc]
__device__ __align__(16) __half g_Wh[DD * DD];   // W rounded to fp16
__device__ int g_ctr;                     // tile queue head
__device__ int g_arr[BB];                 // per-batch arrival counts

// ---------------- smem layout (dynamic), bytes -----------------------------
#define SM_BIAS   0             // 256 f
#define SM_ATTN   1024          // 256 f
#define SM_RED    2048          // 512 f (score red, then p[] weights)
#define SM_A      4096          // A double buffer: 2 stages x 10240
#define A_STRIDE  80            // 32 fp16 padded: stride/16 odd -> ldmatrix conflict-free
#define OFF_ALO   10240         // NOTE: lo plane offset WITHIN combined A-stage? (see below)
#define A_STG     10240         // one A plane-pair stage: hi 5120? -- defined concretely below
// A stage layout: 128 rows x 80B hi plane (10240)?? We need hi+lo:
// stage s occupies [SM_A + s*20480, +20480): hi at +0 (128x80=10240), lo at +10240.
#define A_STAGE_BYTES 20480
#define SM_W      (SM_A + 2*A_STAGE_BYTES)          // 45056
#define W_REGION  20480                              // 256 rows x 80B per K-chunk
#define SM_SCR    (SM_W + 8*W_REGION)                // 208896: mw(64B) zw(64B) ints(16B)
#define SMEM_BYTES (SM_SCR + 192)                    // 209088

// ---------------- PTX helpers (baseline ISA only: sm_80-class) -------------
__device__ __forceinline__ uint32_t smem_u32(const void* p) {
    uint32_t a;
    asm("{ .reg .u64 t; cvta.to.shared.u64 t, %1; cvt.u32.u64 %0, t; }" : "=r"(a) : "l"(p));
    return a;
}
__device__ __forceinline__ void ldsm4(uint32_t* r, uint32_t addr) {
    asm volatile("ldmatrix.sync.aligned.m8n8.x4.shared.b16 {%0,%1,%2,%3}, [%4];"
                 : "=r"(r[0]), "=r"(r[1]), "=r"(r[2]), "=r"(r[3]) : "r"(addr));
}
__device__ __forceinline__ void mma_f16(float* d, const uint32_t* a, const uint32_t* b) {
    asm volatile("mma.sync.aligned.m16n8k16.row.col.f32.f16.f16.f32 "
                 "{%0,%1,%2,%3}, {%4,%5,%6,%7}, {%8,%9}, {%0,%1,%2,%3};"
                 : "+f"(d[0]), "+f"(d[1]), "+f"(d[2]), "+f"(d[3])
                 : "r"(a[0]), "r"(a[1]), "r"(a[2]), "r"(a[3]), "r"(b[0]), "r"(b[1]));
}
#define CP16(dst, src) asm volatile("cp.async.cg.shared.global [%0], [%1], 16;" :: "r"(dst), "l"(src))
#define CP_COMMIT()    asm volatile("cp.async.commit_group;" ::: "memory")
#define CP_WAIT0()     asm volatile("cp.async.wait_group 0;" ::: "memory")

__device__ __forceinline__ uint32_t pk2h(float a, float b) {
    __half2 h = __floats2half2_rn(a, b);
    return *(uint32_t*)&h;
}

// ---------------------------------------------------------------------------
// Kernel 0: round W to fp16 + reset queue/arrival counters.
// ---------------------------------------------------------------------------
__global__ void prep_kernel(const float* __restrict__ W)
{
    if (blockIdx.x == 0) {
        if (threadIdx.x == 0) g_ctr = 0;
        if (threadIdx.x < BB) g_arr[threadIdx.x] = 0;
    }
    int i = blockIdx.x * blockDim.x + threadIdx.x;   // 16384 float4 units
    float4 w = ((const float4*)W)[i];
    uint2 hp;
    hp.x = pk2h(w.x, w.y);
    hp.y = pk2h(w.z, w.w);
    ((uint2*)g_Wh)[i] = hp;
}

// ---------------------------------------------------------------------------
// Kernel 1: persistent-CTA fp16 2-term split GEMM (z = Ah*Wh + Al*Wh) with
// W resident in smem (loaded once per CTA), tiles pulled from an atomic
// queue, fused online-softmax stats, and inline per-batch finalization by
// the last-arriving CTA.
// ---------------------------------------------------------------------------
__global__ __launch_bounds__(512, 1)
void score_kernel(const float* __restrict__ x, const int* __restrict__ mask,
                  const float* __restrict__ bias, const float* __restrict__ attn,
                  float* __restrict__ out)
{
    extern __shared__ char smem[];
    const uint32_t sb = smem_u32(smem);
    const int tid = threadIdx.x;
    const int lane = tid & 31;
    const int wid = tid >> 5;
    const int wm = wid & 3;          // M quarter (32 rows)
    const int wn = wid >> 2;         // N quarter (64 cols)

    if (tid < 256) {
        ((float*)(smem + SM_BIAS))[tid] = bias[tid];
        ((float*)(smem + SM_ATTN))[tid] = attn[tid];
    }

    // ---- load ALL of W (fp16, padded stride 80) into smem once ----
#pragma unroll
    for (int i = 0; i < 16; i++) {
        int u = tid + 512 * i;       // 8192 16B-groups
        int n = u >> 5, r5 = u & 31;
        int c = r5 >> 2, g = r5 & 3;
        CP16(sb + SM_W + c * W_REGION + n * A_STRIDE + g * 16,
             &g_Wh[n * DD + c * KC + g * 8]);
    }
    CP_COMMIT(); CP_WAIT0();
    __syncthreads();

    float* mw = (float*)(smem + SM_SCR);
    float* zw = (float*)(smem + SM_SCR + 64);
    int* s_next = (int*)(smem + SM_SCR + 128);
    int* s_flag = (int*)(smem + SM_SCR + 132);

    // ---- A helpers ----
    const int ar = tid >> 3;         // row 0..63 (and +64)
    const int ag = tid & 7;          // float4 group
    const uint32_t a_off = (uint32_t)((wm * 32 + (lane & 15)) * A_STRIDE + (lane >> 4) * 16);
    const uint32_t b_off = (uint32_t)((wn * 64 + (lane & 7) + ((lane >> 4) & 1) * 8) * A_STRIDE
                                      + ((lane >> 3) & 1) * 16);

    // first pop
    if (tid == 0) *s_next = atomicAdd(&g_ctr, 1);
    __syncthreads();
    int t = *s_next;

    while (t < NTILE) {
        const long m0 = (long)t * MT;
        const int b = t / CPB;
        const bool dead = (mask[m0] == 0);

        if (!dead) {
            auto ldA = [&](int c, float4& v0, float4& v1) {
                const float* p = &x[(m0 + ar) * DD + c * KC + ag * 4];
                v0 = *(const float4*)p;
                v1 = *(const float4*)(p + 64 * DD);
            };
            auto stA = [&](float4 v0, float4 v1, int s) {
                char* stg = smem + SM_A + s * A_STAGE_BYTES;
                uint32_t o = (uint32_t)(ar * A_STRIDE + ag * 8);
                uint2 h0, h1, l0, l1;
                __half a, b2;
                a = __float2half(v0.x); b2 = __float2half(v0.y);
                h0.x = pk2h(__half2float(a), __half2float(b2));
                l0.x = pk2h(v0.x - __half2float(a), v0.y - __half2float(b2));
                a = __float2half(v0.z); b2 = __float2half(v0.w);
                h0.y = pk2h(__half2float(a), __half2float(b2));
                l0.y = pk2h(v0.z - __half2float(a), v0.w - __half2float(b2));
                a = __float2half(v1.x); b2 = __float2half(v1.y);
                h1.x = pk2h(__half2float(a), __half2float(b2));
                l1.x = pk2h(v1.x - __half2float(a), v1.y - __half2float(b2));
                a = __float2half(v1.z); b2 = __float2half(v1.w);
                h1.y = pk2h(__half2float(a), __half2float(b2));
                l1.y = pk2h(v1.z - __half2float(a), v1.w - __half2float(b2));
                *(uint2*)(stg + o)                           = h0;
                *(uint2*)(stg + o + 64 * A_STRIDE)           = h1;
                *(uint2*)(stg + OFF_ALO + o)                 = l0;
                *(uint2*)(stg + OFF_ALO + o + 64 * A_STRIDE) = l1;
            };

            float acc[2][8][4];
#pragma unroll
            for (int mt = 0; mt < 2; mt++)
#pragma unroll
                for (int nt = 0; nt < 8; nt++)
#pragma unroll
                    for (int i = 0; i < 4; i++) acc[mt][nt][i] = 0.f;

            auto compute_half = [&](int c, int ks) {
                const uint32_t astg = sb + SM_A + (c & 1) * A_STAGE_BYTES;
                const uint32_t bstg = sb + SM_W + c * W_REGION;
                uint32_t ah[2][4], al[2][4];
#pragma unroll
                for (int mt = 0; mt < 2; mt++) {
                    uint32_t ao = astg + a_off + mt * 16 * A_STRIDE + ks * 32;
                    ldsm4(ah[mt], ao);
                    ldsm4(al[mt], ao + OFF_ALO);
                }
#pragma unroll
                for (int p = 0; p < 4; p++) {
                    uint32_t bh[4];
                    ldsm4(bh, bstg + b_off + p * 16 * A_STRIDE + ks * 32);
#pragma unroll
                    for (int mt = 0; mt < 2; mt++) {
                        mma_f16(acc[mt][2*p],   ah[mt], bh);
                        mma_f16(acc[mt][2*p],   al[mt], bh);
                        mma_f16(acc[mt][2*p+1], ah[mt], bh + 2);
                        mma_f16(acc[mt][2*p+1], al[mt], bh + 2);
                    }
                }
            };

            // ---- per-tile prologue (A only; W is resident) ----
            float4 va0, va1;
            ldA(0, va0, va1);
            stA(va0, va1, 0);
            ldA(1, va0, va1);
            __syncthreads();

#pragma unroll 1
            for (int c = 0; c < NCH; c++) {
                compute_half(c, 0);
                if (c < NCH - 1) {
                    stA(va0, va1, (c + 1) & 1);       // hides under ks=1 HMMAs
                    if (c < NCH - 2) ldA(c + 2, va0, va1);
                }
                compute_half(c, 1);
                if (c < NCH - 1) __syncthreads();
            }

            // ---- score epilogue: attn * tanh(z + bias), reduce over e ----
            const float* bsm = (const float*)(smem + SM_BIAS);
            const float* atm = (const float*)(smem + SM_ATTN);
            float sc[4] = {0.f, 0.f, 0.f, 0.f};
#pragma unroll
            for (int mt = 0; mt < 2; mt++)
#pragma unroll
                for (int nt = 0; nt < 8; nt++) {
                    int e0 = wn * 64 + nt * 8 + 2 * (lane & 3);
                    float b0 = bsm[e0], b1 = bsm[e0 + 1];
                    float a0 = atm[e0], a1 = atm[e0 + 1];
                    sc[mt*2+0] += a0 * tanhf(acc[mt][nt][0] + b0) + a1 * tanhf(acc[mt][nt][1] + b1);
                    sc[mt*2+1] += a0 * tanhf(acc[mt][nt][2] + b0) + a1 * tanhf(acc[mt][nt][3] + b1);
                }
#pragma unroll
            for (int off = 1; off <= 2; off <<= 1)
#pragma unroll
                for (int i = 0; i < 4; i++)
                    sc[i] += __shfl_xor_sync(0xffffffffu, sc[i], off);

            float* red = (float*)(smem + SM_RED);
            __syncthreads();                 // ensure mainloop smem reads done
            if ((lane & 3) == 0) {
                int r = wm * 32 + (lane >> 2);
                red[wn * 128 + r + 0]  = sc[0];
                red[wn * 128 + r + 8]  = sc[1];
                red[wn * 128 + r + 16] = sc[2];
                red[wn * 128 + r + 24] = sc[3];
            }
            __syncthreads();

            // ---- online-softmax over this tile's 128 frames ----
            float s_t = 0.f;
            int valid = 0;
            if (tid < 128) {
                s_t = red[tid] + red[128 + tid] + red[256 + tid] + red[384 + tid];
                valid = mask[m0 + tid];
            }
            float ml = (tid < 128 && valid) ? s_t : -3.0e38f;
#pragma unroll
            for (int off = 16; off >= 1; off >>= 1)
                ml = fmaxf(ml, __shfl_xor_sync(0xffffffffu, ml, off));
            if (lane == 0) mw[wid] = ml;
            __syncthreads();
            float mloc = mw[0];
#pragma unroll
            for (int i = 1; i < 16; i++) mloc = fmaxf(mloc, mw[i]);

            float* psh = (float*)(smem + SM_RED);
            float pz = 0.f;
            if (tid < 128) {
                pz = valid ? __expf(s_t - mloc) : 0.f;
                psh[tid] = pz;
            }
#pragma unroll
            for (int off = 16; off >= 1; off >>= 1)
                pz += __shfl_xor_sync(0xffffffffu, pz, off);
            if (lane == 0) zw[wid] = pz;
            __syncthreads();

            // ---- partial weighted stats (x from global, L2-warm) ----
            const int q  = tid & 63;
            const int tg = tid >> 6;
            const float4* xb = (const float4*)(x + m0 * DD) + q;
            float4 mu = {0.f,0.f,0.f,0.f}, m2 = {0.f,0.f,0.f,0.f};
#pragma unroll 4
            for (int tf = tg; tf < MT; tf += 8) {
                float w = psh[tf];
                float4 v = xb[(long)tf * 64];
                mu.x += w*v.x; mu.y += w*v.y; mu.z += w*v.z; mu.w += w*v.w;
                m2.x += w*v.x*v.x; m2.y += w*v.y*v.y; m2.z += w*v.z*v.z; m2.w += w*v.w*v.w;
            }
            float4* bmu = (float4*)(smem + SM_A);    // A stages idle now
            float4* bm2 = bmu + 512;
            bmu[tid] = mu; bm2[tid] = m2;
            __syncthreads();
            if (tid < 64) {
                float4 omu = {0.f,0.f,0.f,0.f}, om2 = {0.f,0.f,0.f,0.f};
#pragma unroll
                for (int g = 0; g < 8; g++) {
                    float4 a = bmu[g * 64 + q];
                    omu.x += a.x; omu.y += a.y; omu.z += a.z; omu.w += a.w;
                    float4 b2 = bm2[g * 64 + q];
                    om2.x += b2.x; om2.y += b2.y; om2.z += b2.z; om2.w += b2.w;
                }
                ((float4*)&g_part[(t * 2) * DD])[q]     = omu;
                ((float4*)&g_part[(t * 2 + 1) * DD])[q] = om2;
            }
            if (tid == 0) {
                float Z = 0.f;
#pragma unroll
                for (int i = 0; i < 16; i++) Z += zw[i];
                g_meta[t * 2]     = mloc;
                g_meta[t * 2 + 1] = Z;
            }
        } else {
            if (tid == 0) {
                g_meta[t * 2]     = -3.0e38f;
                g_meta[t * 2 + 1] = 0.f;
            }
        }

        // ---- arrival + inline finalize by the last CTA of this batch ----
        __threadfence();
        __syncthreads();
        if (tid == 0) {
            int done = atomicAdd(&g_arr[b], 1);
            *s_flag = (done == CPB - 1) ? 1 : 0;
            *s_next = atomicAdd(&g_ctr, 1);
        }
        __syncthreads();
        if (*s_flag) {
            __threadfence();
            if (tid < 256) {
                const int d = tid;
                float M = -3.0e38f;
#pragma unroll
                for (int c = 0; c < CPB; c++) {
                    float zc = g_meta[(b * CPB + c) * 2 + 1];
                    if (zc > 0.f) M = fmaxf(M, g_meta[(b * CPB + c) * 2]);
                }
                float Z = 0.f, muf = 0.f, m2f = 0.f;
#pragma unroll 1
                for (int c = 0; c < CPB; c++) {
                    float zc = g_meta[(b * CPB + c) * 2 + 1];
                    if (zc <= 0.f) continue;
                    float f = __expf(g_meta[(b * CPB + c) * 2] - M);
                    Z   += f * zc;
                    muf += f * g_part[((b * CPB + c) * 2) * DD + d];
                    m2f += f * g_part[((b * CPB + c) * 2 + 1) * DD + d];
                }
                float inv = 1.f / Z;
                muf *= inv; m2f *= inv;
                float var = fmaxf(m2f - muf * muf, 1e-5f);
                out[b * 2 * DD + d]      = muf;
                out[b * 2 * DD + DD + d] = sqrtf(var);
            }
        }
        __syncthreads();
        t = *s_next;
    }
}

// ---------------------------------------------------------------------------
extern "C" void kernel_launch(void* const* d_in, const int* in_sizes, int n_in,
                              void* d_out, int out_size)
{
    const float* xs   = (const float*)d_in[0];
    const int*   mask = (const int*)  d_in[1];
    // d_in[2] = mask2 (unused)
    const float* W    = (const float*)d_in[3];
    const float* bias = (const float*)d_in[4];
    const float* attn = (const float*)d_in[5];
    float* out = (float*)d_out;

    static int smem_set = 0;
    if (!smem_set) {
        cudaFuncSetAttribute(score_kernel, cudaFuncAttributeMaxDynamicSharedMemorySize, SMEM_BYTES);
        smem_set = 1;
    }

    prep_kernel<<<64, 256>>>(W);
    score_kernel<<<GRID, 512, SMEM_BYTES>>>(xs, mask, bias, attn, out);
}